// round 17
// baseline (speedup 1.0000x reference)
#include <cuda_runtime.h>
#include <cuda_bf16.h>
#include <cstddef>

// Problem constants
#define NN    4096          // nodes
#define BB    4             // batch
#define CC    32            // channels
#define TT    12            // time
#define FF    1536          // BT*C features per node
#define DCAP  256           // per-row neighbor capacity (max degree ~120)

typedef unsigned long long ull;

// ---------------- scratch (device globals; no allocations allowed) ----------
// Chebyshev via gather sums only:  s1 = A~*h,  s2 = A~*s1
//   out = h(W0+W1+W2) - s1(W1+4W2) + s2(2W2) + bias
__device__ float g_dinv[NN];
__device__ int   g_len [NN];
__device__ int   g_col [NN * DCAP];
__device__ float         g_h [(size_t)NN * FF];    // fp32 master
__device__ float         g_s1[(size_t)NN * FF];    // A~*h
__device__ float         g_s2[(size_t)NN * FF];    // A~*s1
__device__ unsigned      g_hb [(size_t)NN * FF / 2];  // packed lattice-bf16 pairs
__device__ unsigned      g_s1b[(size_t)NN * FF / 2];

// ---- f32x2 helpers ----------------------------------------------------------
__device__ __forceinline__ ull fpack(float x, float y) {
    ull r; asm("mov.b64 %0, {%1, %2};" : "=l"(r) : "f"(x), "f"(y)); return r;
}
__device__ __forceinline__ ull fdup(float x) {
    ull r; asm("mov.b64 %0, {%1, %1};" : "=l"(r) : "f"(x)); return r;
}
__device__ __forceinline__ void funpack(ull a, float& x, float& y) {
    asm("mov.b64 {%0, %1}, %2;" : "=f"(x), "=f"(y) : "l"(a));
}
__device__ __forceinline__ void ffma2(ull& a, ull v, ull c) {
    asm("fma.rn.f32x2 %0, %1, %2, %0;" : "+l"(a) : "l"(v), "l"(c));
}

// ---- lattice pair encode -----------------------------------------------------
// word = (t<<16)|lo where lo = bf16_rn(v0) bits, t chosen so the whole word,
// read as fp32, is the nearest lattice point to v1 (error <= 2^-8 rel).
__device__ __forceinline__ unsigned enc_pair(float v0, float v1) {
    unsigned lo  = (unsigned)__bfloat16_as_ushort(__float2bfloat16_rn(v0));
    unsigned u   = __float_as_uint(v1);
    unsigned s   = u & 0x80000000u;
    unsigned mag = u & 0x7fffffffu;
    int d = (int)(mag - lo + 0x8000u);
    unsigned tm = (d < 0) ? 0u : ((unsigned)d >> 16);
    if (tm > 0x7fffu) tm = 0x7fffu;
    return s | (tm << 16) | lo;
}

// ---------------- K1: fused CSR build + transpose (independent halves) -------
// blocks [0, 512):     build — 8 warps, one adjacency row each
// blocks [512, 1536):  transpose x[B,C,N,T] -> h[n][f] (fp32 + packed shadow)
__global__ void k_pre(const float* __restrict__ adj,
                      const float* __restrict__ x) {
    __shared__ float sm[32][193];
    if (blockIdx.x < 512) {
        int warp = threadIdx.x >> 5;
        int lane = threadIdx.x & 31;
        int m = blockIdx.x * 8 + warp;
        const float4* row4 = (const float4*)(adj + (size_t)m * NN);
        int* cl = g_col + m * DCAP;
        int base = 0;
        for (int j0 = 0; j0 < NN; j0 += 128) {
            float4 v = row4[(j0 >> 2) + lane];
            unsigned nib = (v.x != 0.f ? 1u : 0u) | (v.y != 0.f ? 2u : 0u)
                         | (v.z != 0.f ? 4u : 0u) | (v.w != 0.f ? 8u : 0u);
            int c = __popc(nib);
            int sc = c;                       // inclusive scan over lanes
            #pragma unroll
            for (int o = 1; o < 32; o <<= 1) {
                int tv = __shfl_up_sync(0xffffffffu, sc, o);
                if (lane >= o) sc += tv;
            }
            int pos = base + sc - c;          // exclusive prefix
            int jb = j0 + 4 * lane;
            if (nib & 1u) { if (pos < DCAP) cl[pos] = jb;     pos++; }
            if (nib & 2u) { if (pos < DCAP) cl[pos] = jb + 1; pos++; }
            if (nib & 4u) { if (pos < DCAP) cl[pos] = jb + 2; pos++; }
            if (nib & 8u) { if (pos < DCAP) cl[pos] = jb + 3; pos++; }
            base += __shfl_sync(0xffffffffu, sc, 31);
        }
        if (lane == 0) {
            g_len[m]  = base < DCAP ? base : DCAP;
            g_dinv[m] = (base > 0) ? rsqrtf((float)base) : 0.f;  // deg == nnz
        }
    } else {
        int tb = blockIdx.x - 512;            // 0..1023
        int n0 = (tb & 255) * 16;
        int b  = tb >> 8;
        for (int idx = threadIdx.x; idx < 32 * 192; idx += 256) {
            int c = idx / 192, r = idx % 192;   // r = n_local*12 + t
            sm[c][r] = x[(((size_t)(b * 32 + c)) * NN + n0) * TT + r];
        }
        __syncthreads();
        for (int idx = threadIdx.x; idx < 16 * 192; idx += 256) {
            int nl  = idx / 192;
            int rem = idx % 192;
            int t  = rem >> 4;
            int c2 = rem & 15;
            int r = nl * TT + t;
            float v0 = sm[2 * c2][r];
            float v1 = sm[2 * c2 + 1][r];
            size_t o = (size_t)(n0 + nl) * FF + (b * TT + t) * 32 + 2 * c2;
            *(float2*)(g_h + o) = make_float2(v0, v1);
            g_hb[o >> 1] = enc_pair(v0, v1);
        }
    }
}

// ---- packed gather-accumulate: 8 features via 4 PRMT + 4 FFMA2 --------------
__device__ __forceinline__ void acc8x2(ull* A, uint4 v, ull cc) {
    asm volatile("{\n\t"
        ".reg .b32 lo;\n\t"
        ".reg .b64 vv;\n\t"
        "prmt.b32 lo, %1, 0, 0x1044;\n\t"
        "mov.b64 vv, {lo, %1};\n\t"
        "fma.rn.f32x2 %0, vv, %2, %0;\n\t"
        "}" : "+l"(A[0]) : "r"(v.x), "l"(cc));
    asm volatile("{\n\t"
        ".reg .b32 lo;\n\t"
        ".reg .b64 vv;\n\t"
        "prmt.b32 lo, %1, 0, 0x1044;\n\t"
        "mov.b64 vv, {lo, %1};\n\t"
        "fma.rn.f32x2 %0, vv, %2, %0;\n\t"
        "}" : "+l"(A[1]) : "r"(v.y), "l"(cc));
    asm volatile("{\n\t"
        ".reg .b32 lo;\n\t"
        ".reg .b64 vv;\n\t"
        "prmt.b32 lo, %1, 0, 0x1044;\n\t"
        "mov.b64 vv, {lo, %1};\n\t"
        "fma.rn.f32x2 %0, vv, %2, %0;\n\t"
        "}" : "+l"(A[2]) : "r"(v.z), "l"(cc));
    asm volatile("{\n\t"
        ".reg .b32 lo;\n\t"
        ".reg .b64 vv;\n\t"
        "prmt.b32 lo, %1, 0, 0x1044;\n\t"
        "mov.b64 vv, {lo, %1};\n\t"
        "fma.rn.f32x2 %0, vv, %2, %0;\n\t"
        "}" : "+l"(A[3]) : "r"(v.w), "l"(cc));
}

// ---- shared SpMM body: batch-of-4 loads, SoA smem entries -------------------
__device__ __forceinline__ void spmm_body(ull* A, const int* s_off,
                                          const float* s_cf, int len,
                                          const char* base) {
    int i = 0;
    for (; i + 4 <= len; i += 4) {
        int4   off = *(const int4*)  (s_off + i);   // one LDS.128: 4 offsets
        float4 cf  = *(const float4*)(s_cf  + i);   // one LDS.128: 4 coefs
        uint4 v0 = __ldg((const uint4*)(base + off.x));
        uint4 v1 = __ldg((const uint4*)(base + off.y));
        uint4 v2 = __ldg((const uint4*)(base + off.z));
        uint4 v3 = __ldg((const uint4*)(base + off.w));
        acc8x2(A, v0, fdup(cf.x));
        acc8x2(A, v1, fdup(cf.y));
        acc8x2(A, v2, fdup(cf.z));
        acc8x2(A, v3, fdup(cf.w));
    }
    for (; i < len; i++) {
        uint4 v = __ldg((const uint4*)(base + s_off[i]));
        acc8x2(A, v, fdup(s_cf[i]));
    }
}

// ---- shared prologue: stage SoA entries, computing coef inline --------------
__device__ __forceinline__ int stage_entries(int m, int* s_off, float* s_cf) {
    int len = g_len[m];
    float dm = g_dinv[m];
    for (int i = threadIdx.x; i < len; i += 192) {
        int j = g_col[m * DCAP + i];
        s_off[i] = j * (FF * 2);
        s_cf [i] = dm * g_dinv[j];
    }
    __syncthreads();
    return len;
}

// ---------------- K2: s1 = norm_adj * h (packed gather, f32x2 math) ----------
__global__ void __launch_bounds__(192) k_spmm1() {
    int m   = blockIdx.x;
    int f0b = threadIdx.x * 16;            // byte offset of this thread's 8 feats
    __shared__ int   s_off[DCAP];
    __shared__ float s_cf [DCAP];
    int len = stage_entries(m, s_off, s_cf);

    ull A[4] = {0ull, 0ull, 0ull, 0ull};
    spmm_body(A, s_off, s_cf, len, (const char*)g_hb + f0b);

    float acc[8];
    funpack(A[0], acc[0], acc[1]);
    funpack(A[1], acc[2], acc[3]);
    funpack(A[2], acc[4], acc[5]);
    funpack(A[3], acc[6], acc[7]);

    size_t fbase = (size_t)m * FF + threadIdx.x * 8;
    *(float4*)(g_s1 + fbase)     = make_float4(acc[0], acc[1], acc[2], acc[3]);
    *(float4*)(g_s1 + fbase + 4) = make_float4(acc[4], acc[5], acc[6], acc[7]);
    uint4 o;
    o.x = enc_pair(acc[0], acc[1]);
    o.y = enc_pair(acc[2], acc[3]);
    o.z = enc_pair(acc[4], acc[5]);
    o.w = enc_pair(acc[6], acc[7]);
    *(uint4*)(g_s1b + (fbase >> 1)) = o;
}

// ---------------- K3: s2 = norm_adj * s1 -------------------------------------
__global__ void __launch_bounds__(192) k_spmm2() {
    int m   = blockIdx.x;
    int f0b = threadIdx.x * 16;
    __shared__ int   s_off[DCAP];
    __shared__ float s_cf [DCAP];
    int len = stage_entries(m, s_off, s_cf);

    ull A[4] = {0ull, 0ull, 0ull, 0ull};
    spmm_body(A, s_off, s_cf, len, (const char*)g_s1b + f0b);

    float acc[8];
    funpack(A[0], acc[0], acc[1]);
    funpack(A[1], acc[2], acc[3]);
    funpack(A[2], acc[4], acc[5]);
    funpack(A[3], acc[6], acc[7]);

    size_t fbase = (size_t)m * FF + threadIdx.x * 8;
    *(float4*)(g_s2 + fbase)     = make_float4(acc[0], acc[1], acc[2], acc[3]);
    *(float4*)(g_s2 + fbase + 4) = make_float4(acc[4], acc[5], acc[6], acc[7]);
}

// ---------------- K4: out = h*(W0+W1+W2) - s1*(W1+4W2) + s2*(2W2) + bias -----
// 1 row per thread, 384 threads, launch_bounds caps regs for >=2 blocks/SM.
__global__ void __launch_bounds__(384, 2) k_out(const float* __restrict__ w,
                                                const float* __restrict__ bias,
                                                float* __restrict__ out) {
    __shared__ float sW[3 * 32 * 32];   // transformed weights [k][c][co]
    __shared__ float sB[32];
    for (int idx = threadIdx.x; idx < 1024; idx += 384) {
        float w0 = w[idx], w1 = w[1024 + idx], w2 = w[2048 + idx];
        sW[idx]        = w0 + w1 + w2;
        sW[1024 + idx] = -(w1 + 4.f * w2);
        sW[2048 + idx] = 2.f * w2;
    }
    if (threadIdx.x < 32) sB[threadIdx.x] = bias[threadIdx.x];
    __syncthreads();

    int b  = blockIdx.y;
    int p  = threadIdx.x;              // (n,t) pair index within 32-node slab
    int na = blockIdx.x * 32 + p / 12;
    int ta = p % 12;

    size_t fba = (size_t)na * FF + (b * TT + ta) * 32;

    ull A[16];                          // 32 co accumulators as f32x2
    #pragma unroll
    for (int q = 0; q < 16; q++) A[q] = fpack(sB[2*q], sB[2*q+1]);

    #pragma unroll
    for (int c4 = 0; c4 < 8; c4++) {
        float4 X0 = __ldg((const float4*)(g_h  + fba + c4 * 4));
        float4 X1 = __ldg((const float4*)(g_s1 + fba + c4 * 4));
        float4 X2 = __ldg((const float4*)(g_s2 + fba + c4 * 4));
        #pragma unroll
        for (int cc = 0; cc < 4; cc++) {
            int c = c4 * 4 + cc;
            ull a0 = fdup(((const float*)&X0)[cc]);
            ull a1 = fdup(((const float*)&X1)[cc]);
            ull a2 = fdup(((const float*)&X2)[cc]);
            const ulonglong2* w0 = (const ulonglong2*)(sW +            c * 32);
            const ulonglong2* w1 = (const ulonglong2*)(sW + 32 * 32 +  c * 32);
            const ulonglong2* w2 = (const ulonglong2*)(sW + 2*32*32 +  c * 32);
            #pragma unroll
            for (int q = 0; q < 8; q++) {
                ulonglong2 W0 = w0[q], W1 = w1[q], W2 = w2[q];
                ffma2(A[2*q],   W0.x, a0); ffma2(A[2*q+1], W0.y, a0);
                ffma2(A[2*q],   W1.x, a1); ffma2(A[2*q+1], W1.y, a1);
                ffma2(A[2*q],   W2.x, a2); ffma2(A[2*q+1], W2.y, a2);
            }
        }
    }
    float* po = out + ((size_t)(b * 32) * NN + na) * TT + ta;
    #pragma unroll
    for (int q = 0; q < 16; q++) {
        float x, y;
        funpack(A[q], x, y);
        po[(size_t)(2*q)     * NN * TT] = x;
        po[(size_t)(2*q + 1) * NN * TT] = y;
    }
}

// ---------------- launch -----------------------------------------------------
extern "C" void kernel_launch(void* const* d_in, const int* in_sizes, int n_in,
                              void* d_out, int out_size) {
    const float* x    = (const float*)d_in[0];   // [4,32,4096,12]
    const float* adj  = (const float*)d_in[1];   // [4096,4096]
    const float* w    = (const float*)d_in[2];   // [3,32,32]
    const float* bias = (const float*)d_in[3];   // [32]
    float* out = (float*)d_out;                  // [4,32,4096,12]

    k_pre   <<<1536, 256>>>(adj, x);
    k_spmm1 <<<NN, 192>>>();
    k_spmm2 <<<NN, 192>>>();
    k_out   <<<dim3(NN / 32, BB), 384>>>(w, bias, out);
}